// round 12
// baseline (speedup 1.0000x reference)
#include <cuda_runtime.h>
#include <cuda_fp16.h>
#include <cstdint>

#define B   32
#define C   128
#define H   64
#define W   64
#define KM  4
#define O   256
#define RED 32
#define HW  4096
#define KDIM 1152
#define NT  1024      // 32x32 output tiles of 2x2 per image

// ---------------- device scratch (module globals, no allocation) ------------
__device__ float g_pooled[B * C];
__device__ float g_att[B * KM];
__device__ __align__(256) __half g_xt[(size_t)B * HW * C];        // [b][pix][c]
__device__ __align__(256) __half g_u[(size_t)B * 16 * O * C];     // [b][xv][o][c]
__device__ __align__(256) __half g_v[(size_t)B * 16 * NT * C];    // [b][xv][t][c]

// ---------------- PTX helpers (family-independent) -------------
__device__ __forceinline__ uint32_t smem_to_u32(const void* p) {
    uint32_t a;
    asm("{ .reg .u64 t; cvta.to.shared.u64 t, %1; cvt.u32.u64 %0, t; }" : "=r"(a) : "l"(p));
    return a;
}
__device__ __forceinline__ void cp_bulk(uint32_t dst, const void* src, uint32_t bytes, uint32_t mbar) {
    asm volatile("cp.async.bulk.shared::cta.global.mbarrier::complete_tx::bytes [%0], [%1], %2, [%3];"
        :: "r"(dst), "l"(src), "r"(bytes), "r"(mbar) : "memory");
}
#define MBARRIER_INIT(mbar, c) \
    asm volatile("mbarrier.init.shared.b64 [%0], %1;" :: "r"((uint32_t)(mbar)), "r"((uint32_t)(c)) : "memory")
#define MBARRIER_INVAL(mbar) \
    asm volatile("mbarrier.inval.shared.b64 [%0];" :: "r"((uint32_t)(mbar)) : "memory")
#define MBARRIER_ARRIVE_EXPECT_TX(mbar, bytes) \
    asm volatile("mbarrier.arrive.expect_tx.shared.b64 _, [%0], %1;" \
        :: "r"((uint32_t)(mbar)), "r"((uint32_t)(bytes)) : "memory")
#define FENCE_PROXY_ASYNC() asm volatile("fence.proxy.async.shared::cta;" ::: "memory")

#define MBARRIER_WAIT_PARITY(mbar_smem_addr, phase_parity) do { \
    uint32_t _mbar = (uint32_t)(mbar_smem_addr); \
    uint32_t _parity = (uint32_t)(phase_parity); \
    uint32_t _done; \
    asm volatile("{\n\t.reg .pred p;\n\t" \
        "mbarrier.try_wait.parity.acquire.cta.shared::cta.b64 p, [%1], %2;\n\t" \
        "selp.b32 %0, 1, 0, p;\n\t}" \
        : "=r"(_done) : "r"(_mbar), "r"(_parity) : "memory"); \
    if (!_done) { \
        asm volatile("{\n\t.reg .pred P1;\n\t" \
            "WAIT_LOOP_%=:\n\t" \
            "mbarrier.try_wait.parity.acquire.cta.shared::cta.b64 P1, [%0], %1, 0x989680;\n\t" \
            "@P1 bra.uni WAIT_DONE_%=;\n\t" \
            "bra.uni WAIT_LOOP_%=;\n\t" \
            "WAIT_DONE_%=:\n\t}" \
            :: "r"(_mbar), "r"(_parity) : "memory"); \
    } \
} while(0)

#define LDSM_X4(r, addr) \
    asm volatile("ldmatrix.sync.aligned.m8n8.x4.shared.b16 {%0,%1,%2,%3}, [%4];" \
        : "=r"((r)[0]), "=r"((r)[1]), "=r"((r)[2]), "=r"((r)[3]) : "r"(addr))

__device__ __forceinline__ void mma16816(float* d, const uint32_t* a, uint32_t b0, uint32_t b1) {
    asm volatile("mma.sync.aligned.m16n8k16.row.col.f32.f16.f16.f32 "
        "{%0,%1,%2,%3}, {%4,%5,%6,%7}, {%8,%9}, {%0,%1,%2,%3};"
        : "+f"(d[0]), "+f"(d[1]), "+f"(d[2]), "+f"(d[3])
        : "r"(a[0]), "r"(a[1]), "r"(a[2]), "r"(a[3]), "r"(b0), "r"(b1));
}

// ---------------------------------------------------------------------------
// 0) zero pooled accumulator
// ---------------------------------------------------------------------------
__global__ void zero_kernel() {
    for (int i = threadIdx.x; i < B * C; i += 128) g_pooled[i] = 0.f;
}

// ---------------------------------------------------------------------------
// 1) x transpose -> xT[b][pix][c] fp16, fused with pooling partials
// ---------------------------------------------------------------------------
__global__ void xt_kernel(const float* __restrict__ x) {
    int b = blockIdx.y;
    int p0 = blockIdx.x * 64;
    __shared__ float sm[64][C + 1];
    const float* xb = x + (size_t)b * C * HW + p0;
    for (int idx = threadIdx.x; idx < 64 * C; idx += 256) {
        int c = idx >> 6, p = idx & 63;
        sm[p][c] = xb[(size_t)c * HW + p];
    }
    __syncthreads();
    __half* oh = g_xt + ((size_t)b * HW + p0) * C;
    for (int idx = threadIdx.x; idx < 64 * C; idx += 256) {
        int p = idx >> 7, c = idx & 127;
        oh[(size_t)p * C + c] = __float2half_rn(sm[p][c]);
    }
    if (threadIdx.x < C) {
        int c = threadIdx.x;
        float s = 0.f;
        #pragma unroll 8
        for (int p = 0; p < 64; p++) s += sm[p][c];
        atomicAdd(&g_pooled[b * C + c], s);
    }
}

// ---------------------------------------------------------------------------
// 2) Attention MLP + softmax (one thread per batch), pooled holds SUMS
// ---------------------------------------------------------------------------
__global__ void attn_kernel(const float* __restrict__ w1, const float* __restrict__ b1,
                            const float* __restrict__ w2, const float* __restrict__ b2) {
    int b = threadIdx.x;
    if (b >= B) return;
    const float inv_hw = 1.f / (float)HW;
    const float* pb = g_pooled + b * C;
    float h[RED];
    #pragma unroll 4
    for (int r = 0; r < RED; r++) {
        float s = 0.f;
        const float* wr = w1 + r * C;
        #pragma unroll 8
        for (int c = 0; c < C; c++) s += pb[c] * wr[c];
        h[r] = fmaxf(s * inv_hw + b1[r], 0.f);
    }
    float logits[KM];
    float mx = -1e30f;
    #pragma unroll
    for (int k = 0; k < KM; k++) {
        float s = b2[k];
        const float* wr = w2 + k * RED;
        #pragma unroll
        for (int r = 0; r < RED; r++) s += h[r] * wr[r];
        logits[k] = s; mx = fmaxf(mx, s);
    }
    float den = 0.f;
    #pragma unroll
    for (int k = 0; k < KM; k++) { logits[k] = __expf(logits[k] - mx); den += logits[k]; }
    float inv = 1.f / den;
    #pragma unroll
    for (int k = 0; k < KM; k++) g_att[b * KM + k] = logits[k] * inv;
}

// ---------------------------------------------------------------------------
// 3) U kernel: mix wk + Winograd filter transform U = G g G^T -> g_u
// ---------------------------------------------------------------------------
__global__ void u_kernel(const float* __restrict__ weights) {
    int o = blockIdx.x, b = blockIdx.y;
    int c = threadIdx.x;
    float a0 = g_att[b * KM + 0], a1 = g_att[b * KM + 1];
    float a2 = g_att[b * KM + 2], a3 = g_att[b * KM + 3];
    const size_t ks = (size_t)O * KDIM;
    const float* wp = weights + (size_t)o * KDIM + c * 9;
    float g[9];
    #pragma unroll
    for (int t = 0; t < 9; t++)
        g[t] = a0 * wp[t] + a1 * wp[ks + t] + a2 * wp[2 * ks + t] + a3 * wp[3 * ks + t];
    float t0[4][3];
    #pragma unroll
    for (int j = 0; j < 3; j++) {
        t0[0][j] = g[j];
        t0[1][j] = 0.5f * (g[j] + g[3 + j] + g[6 + j]);
        t0[2][j] = 0.5f * (g[j] - g[3 + j] + g[6 + j]);
        t0[3][j] = g[6 + j];
    }
    __half* up = g_u + ((size_t)b * 16 * O + o) * C + c;
    const size_t ss = (size_t)O * C;
    #pragma unroll
    for (int xi = 0; xi < 4; xi++) {
        float u0 = t0[xi][0];
        float u1 = 0.5f * (t0[xi][0] + t0[xi][1] + t0[xi][2]);
        float u2 = 0.5f * (t0[xi][0] - t0[xi][1] + t0[xi][2]);
        float u3 = t0[xi][2];
        up[(xi * 4 + 0) * ss] = __float2half_rn(u0);
        up[(xi * 4 + 1) * ss] = __float2half_rn(u1);
        up[(xi * 4 + 2) * ss] = __float2half_rn(u2);
        up[(xi * 4 + 3) * ss] = __float2half_rn(u3);
    }
}

// ---------------------------------------------------------------------------
// 4) V kernel: input transform V = B^T d B per 4x4 patch (stride 2) -> g_v
// ---------------------------------------------------------------------------
#define V_SMEM (4 * 66 * 128 * 2)   // 67584

__global__ void __launch_bounds__(256) v_kernel() {
    extern __shared__ __half sm[];   // [4][66][128], px shifted by +1
    int ty = blockIdx.x, b = blockIdx.y;
    int tid = threadIdx.x;

    #pragma unroll
    for (int i = 0; i < 4; i++) {
        int r = 2 * ty - 1 + i;
        uint4* dst = (uint4*)&sm[(i * 66 + 1) * 128];
        if ((unsigned)r < 64u) {
            const uint4* src = (const uint4*)(g_xt + ((size_t)b * HW + r * 64) * C);
            for (int q = tid; q < 1024; q += 256) dst[q] = src[q];
        } else {
            uint4 z = make_uint4(0, 0, 0, 0);
            for (int q = tid; q < 1024; q += 256) dst[q] = z;
        }
    }
    if (tid < 128) {
        int i = tid >> 5, which = (tid >> 4) & 1, q = tid & 15;
        uint4 z = make_uint4(0, 0, 0, 0);
        ((uint4*)&sm[(i * 66 + which * 65) * 128])[q] = z;
    }
    __syncthreads();

    int tx = tid >> 3;
    int cg = tid & 7;
    __half* vb = g_v + ((size_t)b * 16 * NT + ty * 32 + tx) * C;
    const size_t ss = (size_t)NT * C;

    #pragma unroll
    for (int cc2 = 0; cc2 < 4; cc2++) {
        int c0 = cg * 16 + cc2 * 4;
        __half2 da[4][4], db[4][4];
        #pragma unroll
        for (int i = 0; i < 4; i++)
            #pragma unroll
            for (int j = 0; j < 4; j++) {
                uint2 w = *(const uint2*)&sm[(i * 66 + 2 * tx + j) * 128 + c0];
                da[i][j] = *(__half2*)&w.x;
                db[i][j] = *(__half2*)&w.y;
            }
        __half2 ea[4][4], eb[4][4];
        #pragma unroll
        for (int j = 0; j < 4; j++) {
            ea[0][j] = __hsub2(da[0][j], da[2][j]);
            ea[1][j] = __hadd2(da[1][j], da[2][j]);
            ea[2][j] = __hsub2(da[2][j], da[1][j]);
            ea[3][j] = __hsub2(da[1][j], da[3][j]);
            eb[0][j] = __hsub2(db[0][j], db[2][j]);
            eb[1][j] = __hadd2(db[1][j], db[2][j]);
            eb[2][j] = __hsub2(db[2][j], db[1][j]);
            eb[3][j] = __hsub2(db[1][j], db[3][j]);
        }
        #pragma unroll
        for (int xi = 0; xi < 4; xi++) {
            __half2 va[4], vbv[4];
            va[0] = __hsub2(ea[xi][0], ea[xi][2]);
            va[1] = __hadd2(ea[xi][1], ea[xi][2]);
            va[2] = __hsub2(ea[xi][2], ea[xi][1]);
            va[3] = __hsub2(ea[xi][1], ea[xi][3]);
            vbv[0] = __hsub2(eb[xi][0], eb[xi][2]);
            vbv[1] = __hadd2(eb[xi][1], eb[xi][2]);
            vbv[2] = __hsub2(eb[xi][2], eb[xi][1]);
            vbv[3] = __hsub2(eb[xi][1], eb[xi][3]);
            #pragma unroll
            for (int nu = 0; nu < 4; nu++) {
                uint2 w;
                w.x = *(uint32_t*)&va[nu];
                w.y = *(uint32_t*)&vbv[nu];
                *(uint2*)(vb + (size_t)(xi * 4 + nu) * ss + c0) = w;
            }
        }
    }
}

// ---------------------------------------------------------------------------
// 5) Winograd GEMM v2: CTA 64o x 128t, 256 threads, 8 warps (4M x 2N),
//    warp tile 16o x 64t -> 64 MMAs/warp/stage.  One barrier per stage,
//    fold overlapped with next-stage bulk loads.  16 stages (one xv each).
// ---------------------------------------------------------------------------
#define RPADB 272
#define A_ROWS_G 64
#define B_ROWS_G 128
#define AT_BYTES (A_ROWS_G * RPADB)        // 17408
#define BT_BYTES (B_ROWS_G * RPADB)        // 34816
#define OFF_A 0
#define OFF_B AT_BYTES
#define STAGE_BYTES (AT_BYTES + BT_BYTES)  // 52224
#define STAGE_TX (192u * 256u)             // 49152
#define GEMM_SMEM (1024 + 2 * STAGE_BYTES) // 105472

__global__ void __launch_bounds__(256, 1) wino_gemm(float* __restrict__ out) {
    extern __shared__ char smem[];
    uint32_t sb = smem_to_u32(smem);
    uint32_t mbar0 = sb;
    uint32_t tiles = sb + 1024;
    int tid = threadIdx.x;
    int lane = tid & 31, wid = tid >> 5;
    int b  = blockIdx.z;
    int ob = blockIdx.y * 64;
    int tb = blockIdx.x * 128;
    int wm = (wid & 3) * 16;       // 4 M-groups of 16
    int wn = (wid >> 2) * 64;      // 2 N-groups of 64

    if (tid == 0) { MBARRIER_INIT(mbar0, 1); MBARRIER_INIT(mbar0 + 8, 1); }
    __syncthreads();

    const __half* ub = g_u + ((size_t)b * 16 * O + ob) * C;
    const __half* vb = g_v + ((size_t)b * 16 * NT + tb) * C;

    // ONE syncthreads per stage: it orders (a) all warps' reads of the buffer
    // being overwritten and (b) tid0's expect_tx before any cp_bulk issue.
    auto load_stage = [&](int s) {
        uint32_t mbar = mbar0 + (uint32_t)(s & 1) * 8;
        uint32_t base = tiles + (uint32_t)(s & 1) * STAGE_BYTES;
        FENCE_PROXY_ASYNC();
        if (tid == 0) MBARRIER_ARRIVE_EXPECT_TX(mbar, STAGE_TX);
        __syncthreads();
        if (tid < 64) {
            cp_bulk(base + OFF_A + (uint32_t)tid * RPADB,
                    ub + ((size_t)s * O + tid) * C, 256, mbar);
        } else if (tid < 192) {
            int r = tid - 64;
            cp_bulk(base + OFF_B + (uint32_t)r * RPADB,
                    vb + ((size_t)s * NT + r) * C, 256, mbar);
        }
    };

    float Y[2][2][8][4];
    #pragma unroll
    for (int p = 0; p < 2; p++)
        #pragma unroll
        for (int q = 0; q < 2; q++)
            #pragma unroll
            for (int nt = 0; nt < 8; nt++)
                #pragma unroll
                for (int j = 0; j < 4; j++) Y[p][q][nt][j] = 0.f;

    load_stage(0);
    load_stage(1);

    uint32_t a_row = (uint32_t)(wm + (lane & 15));
    uint32_t a_kb  = (uint32_t)((lane >> 4) * 16);
    uint32_t b_row = (uint32_t)(wn + (lane & 7) + ((lane >> 4) & 1) * 8);
    uint32_t b_kb  = (uint32_t)(((lane >> 3) & 1) * 16);

    #pragma unroll 1
    for (int s = 0; s < 16; s++) {
        MBARRIER_WAIT_PARITY(mbar0 + (uint32_t)(s & 1) * 8, (s >> 1) & 1);
        uint32_t base = tiles + (uint32_t)(s & 1) * STAGE_BYTES;

        float M[8][4];
        #pragma unroll
        for (int nt = 0; nt < 8; nt++)
            #pragma unroll
            for (int j = 0; j < 4; j++) M[nt][j] = 0.f;

        #pragma unroll
        for (int kk = 0; kk < 8; kk++) {
            uint32_t kb = (uint32_t)(kk * 32);
            uint32_t a[4];
            LDSM_X4(a, base + OFF_A + a_row * RPADB + kb + a_kb);
            #pragma unroll
            for (int g = 0; g < 4; g++) {
                uint32_t bh[4];
                LDSM_X4(bh, base + OFF_B + (b_row + g * 16) * RPADB + kb + b_kb);
                mma16816(M[g * 2 + 0], a, bh[0], bh[1]);
                mma16816(M[g * 2 + 1], a, bh[2], bh[3]);
            }
        }

        // issue next-stage loads FIRST (the barrier inside orders reads-done),
        // then fold while the loads fly.
        if (s + 2 < 16) load_stage(s + 2);
        else __syncthreads();

        int xi = s >> 2, nu = s & 3;
        float ax0 = (xi == 3) ? 0.f : 1.f;
        float ax1 = (xi == 0) ? 0.f : ((xi == 1) ? 1.f : -1.f);
        float an0 = (nu == 3) ? 0.f : 1.f;
        float an1 = (nu == 0) ? 0.f : ((nu == 1) ? 1.f : -1.f);
        float w00 = ax0 * an0, w01 = ax0 * an1;
        float w10 = ax1 * an0, w11 = ax1 * an1;
        #pragma unroll
        for (int nt = 0; nt < 8; nt++)
            #pragma unroll
            for (int j = 0; j < 4; j++) {
                float m = M[nt][j];
                Y[0][0][nt][j] += w00 * m;
                Y[0][1][nt][j] += w01 * m;
                Y[1][0][nt][j] += w10 * m;
                Y[1][1][nt][j] += w11 * m;
            }
    }

    // epilogue: Y[p][q] -> out, float4 per (nt,rh,p)
    float* outb = out + (size_t)b * O * HW;
    int o0 = ob + wm + (lane >> 2);
    #pragma unroll
    for (int nt = 0; nt < 8; nt++) {
        int t0 = tb + wn + nt * 8 + 2 * (lane & 3);
        int ty = t0 >> 5, tx = t0 & 31;
        #pragma unroll
        for (int rh = 0; rh < 2; rh++) {
            int o = o0 + rh * 8;
            float* rowb = outb + (size_t)o * HW + 2 * tx;
            #pragma unroll
            for (int p = 0; p < 2; p++) {
                float4 v = make_float4(Y[p][0][nt][2 * rh],     Y[p][1][nt][2 * rh],
                                       Y[p][0][nt][2 * rh + 1], Y[p][1][nt][2 * rh + 1]);
                *(float4*)(rowb + (2 * ty + p) * 64) = v;
            }
        }
    }
    __syncthreads();
    if (tid == 0) { MBARRIER_INVAL(mbar0); MBARRIER_INVAL(mbar0 + 8); }
}

// ---------------------------------------------------------------------------
extern "C" void kernel_launch(void* const* d_in, const int* in_sizes, int n_in,
                              void* d_out, int out_size) {
    const float* x       = (const float*)d_in[0];
    const float* weights = (const float*)d_in[1];
    const float* w1      = (const float*)d_in[2];
    const float* b1      = (const float*)d_in[3];
    const float* w2      = (const float*)d_in[4];
    const float* b2      = (const float*)d_in[5];
    float* out = (float*)d_out;

    zero_kernel<<<1, 128>>>();
    xt_kernel<<<dim3(HW / 64, B), 256>>>(x);
    attn_kernel<<<1, 32>>>(w1, b1, w2, b2);
    u_kernel<<<dim3(O, B), 128>>>(weights);

    cudaFuncSetAttribute(v_kernel, cudaFuncAttributeMaxDynamicSharedMemorySize, V_SMEM);
    v_kernel<<<dim3(32, B), 256, V_SMEM>>>();

    cudaFuncSetAttribute(wino_gemm, cudaFuncAttributeMaxDynamicSharedMemorySize, GEMM_SMEM);
    wino_gemm<<<dim3(NT / 128, O / 64, B), 256, GEMM_SMEM>>>(out);
}

// round 13
// speedup vs baseline: 1.1678x; 1.1678x over previous
#include <cuda_runtime.h>
#include <cuda_fp16.h>
#include <cstdint>

#define B   32
#define C   128
#define H   64
#define W   64
#define KM  4
#define O   256
#define RED 32
#define HW  4096
#define KDIM 1152

// ---------------- device scratch (module globals, no allocation) ------------
__device__ float g_pooled[B * C];          // SUM over pixels (scaled in attn)
__device__ float g_att[B * KM];
__device__ __align__(256) __half g_xt[(size_t)B * HW * C];      // xT [b][pix][c]
__device__ __align__(256) __half g_wk[(size_t)B * O * 9 * C];   // wk [b][o][tap][c]
__device__ __align__(256) __half g_zero[C];                     // 256B of zeros

// ---------------- PTX helpers (family-independent) -------------
__device__ __forceinline__ uint32_t smem_to_u32(const void* p) {
    uint32_t a;
    asm("{ .reg .u64 t; cvta.to.shared.u64 t, %1; cvt.u32.u64 %0, t; }" : "=r"(a) : "l"(p));
    return a;
}
__device__ __forceinline__ void cp_bulk(uint32_t dst, const void* src, uint32_t bytes, uint32_t mbar) {
    asm volatile("cp.async.bulk.shared::cta.global.mbarrier::complete_tx::bytes [%0], [%1], %2, [%3];"
        :: "r"(dst), "l"(src), "r"(bytes), "r"(mbar) : "memory");
}
#define MBARRIER_INIT(mbar, c) \
    asm volatile("mbarrier.init.shared.b64 [%0], %1;" :: "r"((uint32_t)(mbar)), "r"((uint32_t)(c)) : "memory")
#define MBARRIER_INVAL(mbar) \
    asm volatile("mbarrier.inval.shared.b64 [%0];" :: "r"((uint32_t)(mbar)) : "memory")
#define MBARRIER_ARRIVE_EXPECT_TX(mbar, bytes) \
    asm volatile("mbarrier.arrive.expect_tx.shared.b64 _, [%0], %1;" \
        :: "r"((uint32_t)(mbar)), "r"((uint32_t)(bytes)) : "memory")
#define FENCE_PROXY_ASYNC() asm volatile("fence.proxy.async.shared::cta;" ::: "memory")

#define MBARRIER_WAIT_PARITY(mbar_smem_addr, phase_parity) do { \
    uint32_t _mbar = (uint32_t)(mbar_smem_addr); \
    uint32_t _parity = (uint32_t)(phase_parity); \
    uint32_t _done; \
    asm volatile("{\n\t.reg .pred p;\n\t" \
        "mbarrier.try_wait.parity.acquire.cta.shared::cta.b64 p, [%1], %2;\n\t" \
        "selp.b32 %0, 1, 0, p;\n\t}" \
        : "=r"(_done) : "r"(_mbar), "r"(_parity) : "memory"); \
    if (!_done) { \
        asm volatile("{\n\t.reg .pred P1;\n\t" \
            "WAIT_LOOP_%=:\n\t" \
            "mbarrier.try_wait.parity.acquire.cta.shared::cta.b64 P1, [%0], %1, 0x989680;\n\t" \
            "@P1 bra.uni WAIT_DONE_%=;\n\t" \
            "bra.uni WAIT_LOOP_%=;\n\t" \
            "WAIT_DONE_%=:\n\t}" \
            :: "r"(_mbar), "r"(_parity) : "memory"); \
    } \
} while(0)

#define LDSM_X4(r, addr) \
    asm volatile("ldmatrix.sync.aligned.m8n8.x4.shared.b16 {%0,%1,%2,%3}, [%4];" \
        : "=r"((r)[0]), "=r"((r)[1]), "=r"((r)[2]), "=r"((r)[3]) : "r"(addr))

__device__ __forceinline__ void mma16816(float* d, const uint32_t* a, uint32_t b0, uint32_t b1) {
    asm volatile("mma.sync.aligned.m16n8k16.row.col.f32.f16.f16.f32 "
        "{%0,%1,%2,%3}, {%4,%5,%6,%7}, {%8,%9}, {%0,%1,%2,%3};"
        : "+f"(d[0]), "+f"(d[1]), "+f"(d[2]), "+f"(d[3])
        : "r"(a[0]), "r"(a[1]), "r"(a[2]), "r"(a[3]), "r"(b0), "r"(b1));
}

// ---------------------------------------------------------------------------
// 0) zero the pooled accumulator
// ---------------------------------------------------------------------------
__global__ void zero_kernel() {
    for (int i = threadIdx.x; i < B * C; i += 128) g_pooled[i] = 0.f;
}

// ---------------------------------------------------------------------------
// 1) x transpose -> xT[b][pix][c] fp16 + pooling partials.
//    Vectorized: float4 loads, uint4 (8-half) stores.
// ---------------------------------------------------------------------------
__global__ void __launch_bounds__(256) xt_kernel(const float* __restrict__ x) {
    int b = blockIdx.y;
    int p0 = blockIdx.x * 64;
    __shared__ float sm[64][C + 1];
    const float* xb = x + (size_t)b * C * HW + p0;

    // load 128c x 64p as float4 over pixels (2048 float4 total)
    #pragma unroll
    for (int i = 0; i < 8; i++) {
        int t = i * 256 + threadIdx.x;        // 0..2047
        int c = t >> 4;
        int p = (t & 15) * 4;
        float4 v = *(const float4*)(xb + (size_t)c * HW + p);
        sm[p + 0][c] = v.x;
        sm[p + 1][c] = v.y;
        sm[p + 2][c] = v.z;
        sm[p + 3][c] = v.w;
    }
    __syncthreads();

    // store 64p x 128c as uint4 (8 halves each; 1024 stores)
    __half* oh = g_xt + ((size_t)b * HW + p0) * C;
    #pragma unroll
    for (int i = 0; i < 4; i++) {
        int t = i * 256 + threadIdx.x;        // 0..1023
        int p = t >> 4;
        int c0 = (t & 15) * 8;
        __half hb[8];
        #pragma unroll
        for (int j = 0; j < 8; j++) hb[j] = __float2half_rn(sm[p][c0 + j]);
        *(uint4*)(oh + (size_t)p * C + c0) = *(const uint4*)hb;
    }

    // pooling partial: thread c sums the 64 pixels of channel c
    if (threadIdx.x < C) {
        int c = threadIdx.x;
        float s = 0.f;
        #pragma unroll 8
        for (int p = 0; p < 64; p++) s += sm[p][c];
        atomicAdd(&g_pooled[b * C + c], s);
    }
}

// ---------------------------------------------------------------------------
// 2) Attention MLP + softmax (one thread per batch).  pooled holds SUMS.
// ---------------------------------------------------------------------------
__global__ void attn_kernel(const float* __restrict__ w1, const float* __restrict__ b1,
                            const float* __restrict__ w2, const float* __restrict__ b2) {
    int b = threadIdx.x;
    if (b >= B) return;
    const float inv_hw = 1.f / (float)HW;
    const float* pb = g_pooled + b * C;
    float h[RED];
    #pragma unroll 4
    for (int r = 0; r < RED; r++) {
        float s = 0.f;
        const float* wr = w1 + r * C;
        #pragma unroll 8
        for (int c = 0; c < C; c++) s += pb[c] * wr[c];
        h[r] = fmaxf(s * inv_hw + b1[r], 0.f);
    }
    float logits[KM];
    float mx = -1e30f;
    #pragma unroll
    for (int k = 0; k < KM; k++) {
        float s = b2[k];
        const float* wr = w2 + k * RED;
        #pragma unroll
        for (int r = 0; r < RED; r++) s += h[r] * wr[r];
        logits[k] = s; mx = fmaxf(mx, s);
    }
    float den = 0.f;
    #pragma unroll
    for (int k = 0; k < KM; k++) { logits[k] = __expf(logits[k] - mx); den += logits[k]; }
    float inv = 1.f / den;
    #pragma unroll
    for (int k = 0; k < KM; k++) g_att[b * KM + k] = logits[k] * inv;
}

// ---------------------------------------------------------------------------
// 3) wk mix -> [b][o][tap][c] fp16.  One block per (o, b), 128 threads.
// ---------------------------------------------------------------------------
__global__ void wk_kernel(const float* __restrict__ weights) {
    int o = blockIdx.x, b = blockIdx.y;
    float a0 = g_att[b * KM + 0], a1 = g_att[b * KM + 1];
    float a2 = g_att[b * KM + 2], a3 = g_att[b * KM + 3];
    __shared__ __half sh[9 * C];
    const size_t ks = (size_t)O * KDIM;
    const float* wp = weights + (size_t)o * KDIM;
    for (int i = threadIdx.x; i < KDIM; i += 128) {
        float v = a0 * wp[i] + a1 * wp[ks + i] + a2 * wp[2 * ks + i] + a3 * wp[3 * ks + i];
        int c = i / 9, tap = i - c * 9;          // weights inner layout [c][tap]
        sh[tap * C + c] = __float2half_rn(v);
    }
    __syncthreads();
    size_t ob = ((size_t)b * O + o) * KDIM;
    uint4* dh = (uint4*)(g_wk + ob);
    const uint4* shv = (const uint4*)sh;
    for (int i = threadIdx.x; i < (KDIM * 2) / 16; i += 128) dh[i] = shv[i];
}

// ---------------------------------------------------------------------------
// 4) Conv GEMM via mma.sync fp16 (fp32 acc) — r9 best-known config.
//    CTA: M=128 x N=128, 256 threads (8 warps), warp tile 32x64 (4M x 2N).
//    Single-stage buffer, 2 CTAs/SM co-residency does the double buffering.
//    9 stages (one tap each, K=128), cp.async.bulk 256B rows.
// ---------------------------------------------------------------------------
#define RPADB   272
#define A_ROWS  128
#define B_ROWS  128
#define AT_BYTES (A_ROWS * RPADB)         // 34816
#define BT_BYTES (B_ROWS * RPADB)         // 34816
#define OFF_A   0
#define OFF_B   (AT_BYTES)
#define STAGE_BYTES (AT_BYTES + BT_BYTES) // 69632
#define NSTAGE  9
#define STAGE_TX (256u * 256u)            // 65536 bytes per stage
#define CONV_SMEM (1024 + STAGE_BYTES)    // 70656

__global__ void __launch_bounds__(256, 2) conv_kernel(float* __restrict__ out) {
    extern __shared__ char smem[];
    uint32_t sb = smem_to_u32(smem);
    uint32_t mbar = sb;
    uint32_t tiles = sb + 1024;
    int tid = threadIdx.x;
    int lane = tid & 31, wid = tid >> 5;
    int b  = blockIdx.z;
    int m0 = blockIdx.y * 128;
    int n0 = blockIdx.x * 128;
    int wm = (wid & 3) * 32;       // warp M offset (4 M-groups)
    int wn = (wid >> 2) * 64;      // warp N offset (2 N-groups)

    if (tid == 0) MBARRIER_INIT(mbar, 1);
    __syncthreads();

    const __half* wk = g_wk + ((size_t)b * O + m0) * KDIM;
    const __half* xt = g_xt + (size_t)b * HW * C;

    auto load_stage = [&](int s) {
        FENCE_PROXY_ASYNC();
        if (tid == 0) MBARRIER_ARRIVE_EXPECT_TX(mbar, STAGE_TX);
        __syncthreads();
        int tap = s;
        int dy = tap / 3 - 1, dx = tap % 3 - 1;
        if (tid < 128) {
            cp_bulk(tiles + OFF_A + (uint32_t)tid * RPADB,
                    wk + (size_t)tid * KDIM + (size_t)tap * C, 256, mbar);
        } else {
            int row = tid - 128;
            int p = n0 + row;
            int iy = (p >> 6) + dy, ix = (p & 63) + dx;
            bool valid = ((unsigned)iy < 64u) && ((unsigned)ix < 64u);
            const __half* src = valid ? (xt + (size_t)(p + dy * 64 + dx) * C) : g_zero;
            cp_bulk(tiles + OFF_B + (uint32_t)row * RPADB, src, 256, mbar);
        }
    };

    float acc[2][8][4];
    #pragma unroll
    for (int i = 0; i < 2; i++)
        #pragma unroll
        for (int j = 0; j < 8; j++)
            #pragma unroll
            for (int q = 0; q < 4; q++) acc[i][j][q] = 0.f;

    load_stage(0);

    uint32_t a_row = (uint32_t)(wm + (lane & 15));
    uint32_t a_kb  = (uint32_t)((lane >> 4) * 16);
    uint32_t b_row = (uint32_t)(wn + (lane & 7) + ((lane >> 4) & 1) * 8);
    uint32_t b_kb  = (uint32_t)(((lane >> 3) & 1) * 16);

    #pragma unroll 1
    for (int s = 0; s < NSTAGE; s++) {
        MBARRIER_WAIT_PARITY(mbar, s & 1);

        #pragma unroll
        for (int kk = 0; kk < 8; kk++) {
            uint32_t kb = (uint32_t)(kk * 32);      // k16 step = 32B
            uint32_t ah[2][4];
            #pragma unroll
            for (int mt = 0; mt < 2; mt++) {
                uint32_t off = (a_row + mt * 16) * RPADB + kb + a_kb;
                LDSM_X4(ah[mt], tiles + OFF_A + off);
            }
            #pragma unroll
            for (int g = 0; g < 4; g++) {
                uint32_t off = (b_row + g * 16) * RPADB + kb + b_kb;
                uint32_t bh[4];
                LDSM_X4(bh, tiles + OFF_B + off);
                #pragma unroll
                for (int mt = 0; mt < 2; mt++) {
                    #pragma unroll
                    for (int nt = 0; nt < 2; nt++) {
                        mma16816(acc[mt][g * 2 + nt], ah[mt], bh[nt * 2], bh[nt * 2 + 1]);
                    }
                }
            }
        }
        __syncthreads();                 // all reads of the single buffer done
        if (s + 1 < NSTAGE) load_stage(s + 1);
    }

    // epilogue: warp writes 32x64 block
    float* ob = out + ((size_t)b * O + m0) * HW + n0;
    #pragma unroll
    for (int mt = 0; mt < 2; mt++) {
        int r = wm + mt * 16 + (lane >> 2);
        #pragma unroll
        for (int nti = 0; nti < 8; nti++) {
            int cn = wn + nti * 8 + 2 * (lane & 3);
            float2 v0 = make_float2(acc[mt][nti][0], acc[mt][nti][1]);
            float2 v1 = make_float2(acc[mt][nti][2], acc[mt][nti][3]);
            *(float2*)(ob + (size_t)r * HW + cn) = v0;
            *(float2*)(ob + (size_t)(r + 8) * HW + cn) = v1;
        }
    }
    __syncthreads();
    if (tid == 0) MBARRIER_INVAL(mbar);
}

// ---------------------------------------------------------------------------
extern "C" void kernel_launch(void* const* d_in, const int* in_sizes, int n_in,
                              void* d_out, int out_size) {
    const float* x       = (const float*)d_in[0];
    const float* weights = (const float*)d_in[1];
    const float* w1      = (const float*)d_in[2];
    const float* b1      = (const float*)d_in[3];
    const float* w2      = (const float*)d_in[4];
    const float* b2      = (const float*)d_in[5];
    float* out = (float*)d_out;

    zero_kernel<<<1, 128>>>();
    xt_kernel<<<dim3(HW / 64, B), 256>>>(x);
    attn_kernel<<<1, 32>>>(w1, b1, w2, b2);
    wk_kernel<<<dim3(O, B), 128>>>(weights);

    cudaFuncSetAttribute(conv_kernel, cudaFuncAttributeMaxDynamicSharedMemorySize, CONV_SMEM);
    conv_kernel<<<dim3(HW / 128, O / 128, B), 256, CONV_SMEM>>>(out);
}

// round 14
// speedup vs baseline: 1.1837x; 1.0137x over previous
#include <cuda_runtime.h>
#include <cuda_fp16.h>
#include <cstdint>

#define B   32
#define C   128
#define H   64
#define W   64
#define KM  4
#define O   256
#define RED 32
#define HW  4096
#define KDIM 1152

// ---------------- device scratch (module globals, no allocation) ------------
__device__ float g_pooled[B * C];          // SUM over pixels (scaled in attn)
__device__ float g_att[B * KM];
__device__ __align__(256) __half g_xt[(size_t)B * HW * C];      // xT [b][pix][c]
__device__ __align__(256) __half g_wk[(size_t)B * O * 9 * C];   // wk [b][o][tap][c]
__device__ __align__(256) __half g_zero[C];                     // 256B of zeros

// ---------------- PTX helpers (family-independent) -------------
__device__ __forceinline__ uint32_t smem_to_u32(const void* p) {
    uint32_t a;
    asm("{ .reg .u64 t; cvta.to.shared.u64 t, %1; cvt.u32.u64 %0, t; }" : "=r"(a) : "l"(p));
    return a;
}
__device__ __forceinline__ void cp_bulk(uint32_t dst, const void* src, uint32_t bytes, uint32_t mbar) {
    asm volatile("cp.async.bulk.shared::cta.global.mbarrier::complete_tx::bytes [%0], [%1], %2, [%3];"
        :: "r"(dst), "l"(src), "r"(bytes), "r"(mbar) : "memory");
}
#define MBARRIER_INIT(mbar, c) \
    asm volatile("mbarrier.init.shared.b64 [%0], %1;" :: "r"((uint32_t)(mbar)), "r"((uint32_t)(c)) : "memory")
#define MBARRIER_INVAL(mbar) \
    asm volatile("mbarrier.inval.shared.b64 [%0];" :: "r"((uint32_t)(mbar)) : "memory")
#define MBARRIER_ARRIVE_EXPECT_TX(mbar, bytes) \
    asm volatile("mbarrier.arrive.expect_tx.shared.b64 _, [%0], %1;" \
        :: "r"((uint32_t)(mbar)), "r"((uint32_t)(bytes)) : "memory")
#define FENCE_PROXY_ASYNC() asm volatile("fence.proxy.async.shared::cta;" ::: "memory")

#define MBARRIER_WAIT_PARITY(mbar_smem_addr, phase_parity) do { \
    uint32_t _mbar = (uint32_t)(mbar_smem_addr); \
    uint32_t _parity = (uint32_t)(phase_parity); \
    uint32_t _done; \
    asm volatile("{\n\t.reg .pred p;\n\t" \
        "mbarrier.try_wait.parity.acquire.cta.shared::cta.b64 p, [%1], %2;\n\t" \
        "selp.b32 %0, 1, 0, p;\n\t}" \
        : "=r"(_done) : "r"(_mbar), "r"(_parity) : "memory"); \
    if (!_done) { \
        asm volatile("{\n\t.reg .pred P1;\n\t" \
            "WAIT_LOOP_%=:\n\t" \
            "mbarrier.try_wait.parity.acquire.cta.shared::cta.b64 P1, [%0], %1, 0x989680;\n\t" \
            "@P1 bra.uni WAIT_DONE_%=;\n\t" \
            "bra.uni WAIT_LOOP_%=;\n\t" \
            "WAIT_DONE_%=:\n\t}" \
            :: "r"(_mbar), "r"(_parity) : "memory"); \
    } \
} while(0)

#define LDSM_X4(r, addr) \
    asm volatile("ldmatrix.sync.aligned.m8n8.x4.shared.b16 {%0,%1,%2,%3}, [%4];" \
        : "=r"((r)[0]), "=r"((r)[1]), "=r"((r)[2]), "=r"((r)[3]) : "r"(addr))

__device__ __forceinline__ void mma16816(float* d, const uint32_t* a, uint32_t b0, uint32_t b1) {
    asm volatile("mma.sync.aligned.m16n8k16.row.col.f32.f16.f16.f32 "
        "{%0,%1,%2,%3}, {%4,%5,%6,%7}, {%8,%9}, {%0,%1,%2,%3};"
        : "+f"(d[0]), "+f"(d[1]), "+f"(d[2]), "+f"(d[3])
        : "r"(a[0]), "r"(a[1]), "r"(a[2]), "r"(a[3]), "r"(b0), "r"(b1));
}

// ---------------------------------------------------------------------------
// 0) zero the pooled accumulator
// ---------------------------------------------------------------------------
__global__ void zero_kernel() {
    for (int i = threadIdx.x; i < B * C; i += 128) g_pooled[i] = 0.f;
}

// ---------------------------------------------------------------------------
// 1) x transpose -> xT[b][pix][c] fp16 + pooling partials.
//    Vectorized: float4 loads, uint4 (8-half) stores.
// ---------------------------------------------------------------------------
__global__ void __launch_bounds__(256) xt_kernel(const float* __restrict__ x) {
    int b = blockIdx.y;
    int p0 = blockIdx.x * 64;
    __shared__ float sm[64][C + 1];
    const float* xb = x + (size_t)b * C * HW + p0;

    #pragma unroll
    for (int i = 0; i < 8; i++) {
        int t = i * 256 + threadIdx.x;        // 0..2047
        int c = t >> 4;
        int p = (t & 15) * 4;
        float4 v = *(const float4*)(xb + (size_t)c * HW + p);
        sm[p + 0][c] = v.x;
        sm[p + 1][c] = v.y;
        sm[p + 2][c] = v.z;
        sm[p + 3][c] = v.w;
    }
    __syncthreads();

    __half* oh = g_xt + ((size_t)b * HW + p0) * C;
    #pragma unroll
    for (int i = 0; i < 4; i++) {
        int t = i * 256 + threadIdx.x;        // 0..1023
        int p = t >> 4;
        int c0 = (t & 15) * 8;
        __half hb[8];
        #pragma unroll
        for (int j = 0; j < 8; j++) hb[j] = __float2half_rn(sm[p][c0 + j]);
        *(uint4*)(oh + (size_t)p * C + c0) = *(const uint4*)hb;
    }

    if (threadIdx.x < C) {
        int c = threadIdx.x;
        float s = 0.f;
        #pragma unroll 8
        for (int p = 0; p < 64; p++) s += sm[p][c];
        atomicAdd(&g_pooled[b * C + c], s);
    }
}

// ---------------------------------------------------------------------------
// 2) Attention MLP + softmax (one thread per batch).  pooled holds SUMS.
// ---------------------------------------------------------------------------
__global__ void attn_kernel(const float* __restrict__ w1, const float* __restrict__ b1,
                            const float* __restrict__ w2, const float* __restrict__ b2) {
    int b = threadIdx.x;
    if (b >= B) return;
    const float inv_hw = 1.f / (float)HW;
    const float* pb = g_pooled + b * C;
    float h[RED];
    #pragma unroll 4
    for (int r = 0; r < RED; r++) {
        float s = 0.f;
        const float* wr = w1 + r * C;
        #pragma unroll 8
        for (int c = 0; c < C; c++) s += pb[c] * wr[c];
        h[r] = fmaxf(s * inv_hw + b1[r], 0.f);
    }
    float logits[KM];
    float mx = -1e30f;
    #pragma unroll
    for (int k = 0; k < KM; k++) {
        float s = b2[k];
        const float* wr = w2 + k * RED;
        #pragma unroll
        for (int r = 0; r < RED; r++) s += h[r] * wr[r];
        logits[k] = s; mx = fmaxf(mx, s);
    }
    float den = 0.f;
    #pragma unroll
    for (int k = 0; k < KM; k++) { logits[k] = __expf(logits[k] - mx); den += logits[k]; }
    float inv = 1.f / den;
    #pragma unroll
    for (int k = 0; k < KM; k++) g_att[b * KM + k] = logits[k] * inv;
}

// ---------------------------------------------------------------------------
// 3) wk mix -> [b][o][tap][c] fp16.  One block per o; weights read ONCE,
//    all 32 batches produced from smem.  128 threads (one channel each).
// ---------------------------------------------------------------------------
__global__ void __launch_bounds__(128) wk_kernel(const float* __restrict__ weights) {
    int o = blockIdx.x;
    __shared__ float w4[4 * KDIM];     // 18.4KB: all 4 kernel variants for this o
    __shared__ float att_s[B * KM];    // 128 att values
    const size_t ks = (size_t)O * KDIM;
    const float* wp = weights + (size_t)o * KDIM;

    // coalesced stage of the 4 weight slices
    for (int i = threadIdx.x; i < 4 * KDIM; i += 128) {
        int k = i / KDIM, j = i - k * KDIM;
        w4[i] = wp[k * ks + j];
    }
    if (threadIdx.x < B * KM) att_s[threadIdx.x] = g_att[threadIdx.x];
    __syncthreads();

    int c = threadIdx.x;               // channel 0..127
    // per-thread weights: [k][tap] for this (o, c)
    float wr[4][9];
    #pragma unroll
    for (int k = 0; k < 4; k++)
        #pragma unroll
        for (int t = 0; t < 9; t++)
            wr[k][t] = w4[k * KDIM + c * 9 + t];   // inner layout [c][tap]

    #pragma unroll 1
    for (int b = 0; b < B; b++) {
        float a0 = att_s[b * KM + 0], a1 = att_s[b * KM + 1];
        float a2 = att_s[b * KM + 2], a3 = att_s[b * KM + 3];
        __half* dst = g_wk + ((size_t)b * O + o) * KDIM + c;
        #pragma unroll
        for (int t = 0; t < 9; t++) {
            float v = a0 * wr[0][t] + a1 * wr[1][t] + a2 * wr[2][t] + a3 * wr[3][t];
            dst[t * C] = __float2half_rn(v);
        }
    }
}

// ---------------------------------------------------------------------------
// 4) Conv GEMM via mma.sync fp16 (fp32 acc) — best-known config (r9/r13).
//    CTA: M=128 x N=128, 256 threads (8 warps), warp tile 32x64 (4M x 2N).
//    Single-stage buffer, 2 CTAs/SM co-residency does the double buffering.
//    9 stages (one tap each, K=128), cp.async.bulk 256B rows.
// ---------------------------------------------------------------------------
#define RPADB   272
#define A_ROWS  128
#define B_ROWS  128
#define AT_BYTES (A_ROWS * RPADB)         // 34816
#define BT_BYTES (B_ROWS * RPADB)         // 34816
#define OFF_A   0
#define OFF_B   (AT_BYTES)
#define STAGE_BYTES (AT_BYTES + BT_BYTES) // 69632
#define NSTAGE  9
#define STAGE_TX (256u * 256u)            // 65536 bytes per stage
#define CONV_SMEM (1024 + STAGE_BYTES)    // 70656

__global__ void __launch_bounds__(256, 2) conv_kernel(float* __restrict__ out) {
    extern __shared__ char smem[];
    uint32_t sb = smem_to_u32(smem);
    uint32_t mbar = sb;
    uint32_t tiles = sb + 1024;
    int tid = threadIdx.x;
    int lane = tid & 31, wid = tid >> 5;
    int b  = blockIdx.z;
    int m0 = blockIdx.y * 128;
    int n0 = blockIdx.x * 128;
    int wm = (wid & 3) * 32;       // warp M offset (4 M-groups)
    int wn = (wid >> 2) * 64;      // warp N offset (2 N-groups)

    if (tid == 0) MBARRIER_INIT(mbar, 1);
    __syncthreads();

    const __half* wk = g_wk + ((size_t)b * O + m0) * KDIM;
    const __half* xt = g_xt + (size_t)b * HW * C;

    auto load_stage = [&](int s) {
        FENCE_PROXY_ASYNC();
        if (tid == 0) MBARRIER_ARRIVE_EXPECT_TX(mbar, STAGE_TX);
        __syncthreads();
        int tap = s;
        int dy = tap / 3 - 1, dx = tap % 3 - 1;
        if (tid < 128) {
            cp_bulk(tiles + OFF_A + (uint32_t)tid * RPADB,
                    wk + (size_t)tid * KDIM + (size_t)tap * C, 256, mbar);
        } else {
            int row = tid - 128;
            int p = n0 + row;
            int iy = (p >> 6) + dy, ix = (p & 63) + dx;
            bool valid = ((unsigned)iy < 64u) && ((unsigned)ix < 64u);
            const __half* src = valid ? (xt + (size_t)(p + dy * 64 + dx) * C) : g_zero;
            cp_bulk(tiles + OFF_B + (uint32_t)row * RPADB, src, 256, mbar);
        }
    };

    float acc[2][8][4];
    #pragma unroll
    for (int i = 0; i < 2; i++)
        #pragma unroll
        for (int j = 0; j < 8; j++)
            #pragma unroll
            for (int q = 0; q < 4; q++) acc[i][j][q] = 0.f;

    load_stage(0);

    uint32_t a_row = (uint32_t)(wm + (lane & 15));
    uint32_t a_kb  = (uint32_t)((lane >> 4) * 16);
    uint32_t b_row = (uint32_t)(wn + (lane & 7) + ((lane >> 4) & 1) * 8);
    uint32_t b_kb  = (uint32_t)(((lane >> 3) & 1) * 16);

    #pragma unroll 1
    for (int s = 0; s < NSTAGE; s++) {
        MBARRIER_WAIT_PARITY(mbar, s & 1);

        #pragma unroll
        for (int kk = 0; kk < 8; kk++) {
            uint32_t kb = (uint32_t)(kk * 32);      // k16 step = 32B
            uint32_t ah[2][4];
            #pragma unroll
            for (int mt = 0; mt < 2; mt++) {
                uint32_t off = (a_row + mt * 16) * RPADB + kb + a_kb;
                LDSM_X4(ah[mt], tiles + OFF_A + off);
            }
            #pragma unroll
            for (int g = 0; g < 4; g++) {
                uint32_t off = (b_row + g * 16) * RPADB + kb + b_kb;
                uint32_t bh[4];
                LDSM_X4(bh, tiles + OFF_B + off);
                #pragma unroll
                for (int mt = 0; mt < 2; mt++) {
                    #pragma unroll
                    for (int nt = 0; nt < 2; nt++) {
                        mma16816(acc[mt][g * 2 + nt], ah[mt], bh[nt * 2], bh[nt * 2 + 1]);
                    }
                }
            }
        }
        __syncthreads();                 // all reads of the single buffer done
        if (s + 1 < NSTAGE) load_stage(s + 1);
    }

    // epilogue: warp writes 32x64 block
    float* ob = out + ((size_t)b * O + m0) * HW + n0;
    #pragma unroll
    for (int mt = 0; mt < 2; mt++) {
        int r = wm + mt * 16 + (lane >> 2);
        #pragma unroll
        for (int nti = 0; nti < 8; nti++) {
            int cn = wn + nti * 8 + 2 * (lane & 3);
            float2 v0 = make_float2(acc[mt][nti][0], acc[mt][nti][1]);
            float2 v1 = make_float2(acc[mt][nti][2], acc[mt][nti][3]);
            *(float2*)(ob + (size_t)r * HW + cn) = v0;
            *(float2*)(ob + (size_t)(r + 8) * HW + cn) = v1;
        }
    }
    __syncthreads();
    if (tid == 0) MBARRIER_INVAL(mbar);
}

// ---------------------------------------------------------------------------
extern "C" void kernel_launch(void* const* d_in, const int* in_sizes, int n_in,
                              void* d_out, int out_size) {
    const float* x       = (const float*)d_in[0];
    const float* weights = (const float*)d_in[1];
    const float* w1      = (const float*)d_in[2];
    const float* b1      = (const float*)d_in[3];
    const float* w2      = (const float*)d_in[4];
    const float* b2      = (const float*)d_in[5];
    float* out = (float*)d_out;

    zero_kernel<<<1, 128>>>();
    xt_kernel<<<dim3(HW / 64, B), 256>>>(x);
    attn_kernel<<<1, 32>>>(w1, b1, w2, b2);
    wk_kernel<<<O, 128>>>(weights);

    cudaFuncSetAttribute(conv_kernel, cudaFuncAttributeMaxDynamicSharedMemorySize, CONV_SMEM);
    conv_kernel<<<dim3(HW / 128, O / 128, B), 256, CONV_SMEM>>>(out);
}

// round 15
// speedup vs baseline: 1.1882x; 1.0037x over previous
#include <cuda_runtime.h>
#include <cuda_fp16.h>
#include <cstdint>

#define B   32
#define C   128
#define H   64
#define W   64
#define KM  4
#define O   256
#define RED 32
#define HW  4096
#define KDIM 1152

// ---------------- device scratch (module globals, no allocation) ------------
__device__ float g_pooled[B * C];          // SUM over pixels (scaled in attn)
__device__ float g_att[B * KM];
__device__ __align__(256) __half g_xt[(size_t)B * HW * C];      // xT [b][pix][c]
__device__ __align__(256) __half g_wk[(size_t)B * O * 9 * C];   // wk [b][o][tap][c]
__device__ __align__(256) __half g_zero[C];                     // 256B of zeros

// ---------------- PTX helpers (family-independent) -------------
__device__ __forceinline__ uint32_t smem_to_u32(const void* p) {
    uint32_t a;
    asm("{ .reg .u64 t; cvta.to.shared.u64 t, %1; cvt.u32.u64 %0, t; }" : "=r"(a) : "l"(p));
    return a;
}
__device__ __forceinline__ void cp_bulk(uint32_t dst, const void* src, uint32_t bytes, uint32_t mbar) {
    asm volatile("cp.async.bulk.shared::cta.global.mbarrier::complete_tx::bytes [%0], [%1], %2, [%3];"
        :: "r"(dst), "l"(src), "r"(bytes), "r"(mbar) : "memory");
}
#define MBARRIER_INIT(mbar, c) \
    asm volatile("mbarrier.init.shared.b64 [%0], %1;" :: "r"((uint32_t)(mbar)), "r"((uint32_t)(c)) : "memory")
#define MBARRIER_INVAL(mbar) \
    asm volatile("mbarrier.inval.shared.b64 [%0];" :: "r"((uint32_t)(mbar)) : "memory")
#define MBARRIER_ARRIVE_EXPECT_TX(mbar, bytes) \
    asm volatile("mbarrier.arrive.expect_tx.shared.b64 _, [%0], %1;" \
        :: "r"((uint32_t)(mbar)), "r"((uint32_t)(bytes)) : "memory")
#define FENCE_PROXY_ASYNC() asm volatile("fence.proxy.async.shared::cta;" ::: "memory")

#define MBARRIER_WAIT_PARITY(mbar_smem_addr, phase_parity) do { \
    uint32_t _mbar = (uint32_t)(mbar_smem_addr); \
    uint32_t _parity = (uint32_t)(phase_parity); \
    uint32_t _done; \
    asm volatile("{\n\t.reg .pred p;\n\t" \
        "mbarrier.try_wait.parity.acquire.cta.shared::cta.b64 p, [%1], %2;\n\t" \
        "selp.b32 %0, 1, 0, p;\n\t}" \
        : "=r"(_done) : "r"(_mbar), "r"(_parity) : "memory"); \
    if (!_done) { \
        asm volatile("{\n\t.reg .pred P1;\n\t" \
            "WAIT_LOOP_%=:\n\t" \
            "mbarrier.try_wait.parity.acquire.cta.shared::cta.b64 P1, [%0], %1, 0x989680;\n\t" \
            "@P1 bra.uni WAIT_DONE_%=;\n\t" \
            "bra.uni WAIT_LOOP_%=;\n\t" \
            "WAIT_DONE_%=:\n\t}" \
            :: "r"(_mbar), "r"(_parity) : "memory"); \
    } \
} while(0)

#define LDSM_X4(r, addr) \
    asm volatile("ldmatrix.sync.aligned.m8n8.x4.shared.b16 {%0,%1,%2,%3}, [%4];" \
        : "=r"((r)[0]), "=r"((r)[1]), "=r"((r)[2]), "=r"((r)[3]) : "r"(addr))

__device__ __forceinline__ void mma16816(float* d, const uint32_t* a, uint32_t b0, uint32_t b1) {
    asm volatile("mma.sync.aligned.m16n8k16.row.col.f32.f16.f16.f32 "
        "{%0,%1,%2,%3}, {%4,%5,%6,%7}, {%8,%9}, {%0,%1,%2,%3};"
        : "+f"(d[0]), "+f"(d[1]), "+f"(d[2]), "+f"(d[3])
        : "r"(a[0]), "r"(a[1]), "r"(a[2]), "r"(a[3]), "r"(b0), "r"(b1));
}

// ---------------------------------------------------------------------------
// 0) zero the pooled accumulator
// ---------------------------------------------------------------------------
__global__ void zero_kernel() {
    for (int i = threadIdx.x; i < B * C; i += 128) g_pooled[i] = 0.f;
}

// ---------------------------------------------------------------------------
// 1) x transpose -> xT[b][pix][c] fp16 + pooling partials.
// ---------------------------------------------------------------------------
__global__ void __launch_bounds__(256) xt_kernel(const float* __restrict__ x) {
    int b = blockIdx.y;
    int p0 = blockIdx.x * 64;
    __shared__ float sm[64][C + 1];
    const float* xb = x + (size_t)b * C * HW + p0;

    #pragma unroll
    for (int i = 0; i < 8; i++) {
        int t = i * 256 + threadIdx.x;        // 0..2047
        int c = t >> 4;
        int p = (t & 15) * 4;
        float4 v = *(const float4*)(xb + (size_t)c * HW + p);
        sm[p + 0][c] = v.x;
        sm[p + 1][c] = v.y;
        sm[p + 2][c] = v.z;
        sm[p + 3][c] = v.w;
    }
    __syncthreads();

    __half* oh = g_xt + ((size_t)b * HW + p0) * C;
    #pragma unroll
    for (int i = 0; i < 4; i++) {
        int t = i * 256 + threadIdx.x;        // 0..1023
        int p = t >> 4;
        int c0 = (t & 15) * 8;
        __half hb[8];
        #pragma unroll
        for (int j = 0; j < 8; j++) hb[j] = __float2half_rn(sm[p][c0 + j]);
        *(uint4*)(oh + (size_t)p * C + c0) = *(const uint4*)hb;
    }

    if (threadIdx.x < C) {
        int c = threadIdx.x;
        float s = 0.f;
        #pragma unroll 8
        for (int p = 0; p < 64; p++) s += sm[p][c];
        atomicAdd(&g_pooled[b * C + c], s);
    }
}

// ---------------------------------------------------------------------------
// 2) Attention MLP + softmax (one thread per batch).  pooled holds SUMS.
// ---------------------------------------------------------------------------
__global__ void attn_kernel(const float* __restrict__ w1, const float* __restrict__ b1,
                            const float* __restrict__ w2, const float* __restrict__ b2) {
    int b = threadIdx.x;
    if (b >= B) return;
    const float inv_hw = 1.f / (float)HW;
    const float* pb = g_pooled + b * C;
    float h[RED];
    #pragma unroll 4
    for (int r = 0; r < RED; r++) {
        float s = 0.f;
        const float* wr = w1 + r * C;
        #pragma unroll 8
        for (int c = 0; c < C; c++) s += pb[c] * wr[c];
        h[r] = fmaxf(s * inv_hw + b1[r], 0.f);
    }
    float logits[KM];
    float mx = -1e30f;
    #pragma unroll
    for (int k = 0; k < KM; k++) {
        float s = b2[k];
        const float* wr = w2 + k * RED;
        #pragma unroll
        for (int r = 0; r < RED; r++) s += h[r] * wr[r];
        logits[k] = s; mx = fmaxf(mx, s);
    }
    float den = 0.f;
    #pragma unroll
    for (int k = 0; k < KM; k++) { logits[k] = __expf(logits[k] - mx); den += logits[k]; }
    float inv = 1.f / den;
    #pragma unroll
    for (int k = 0; k < KM; k++) g_att[b * KM + k] = logits[k] * inv;
}

// ---------------------------------------------------------------------------
// 3) wk mix -> [b][o][tap][c] fp16.  One block per o; weights read ONCE.
//    160 threads; threads 0..143 = (tap, c-group of 8), one uint4 store
//    per batch per thread (fully coalesced).
// ---------------------------------------------------------------------------
__global__ void __launch_bounds__(160) wk_kernel(const float* __restrict__ weights) {
    int o = blockIdx.x;
    __shared__ float w4[4 * KDIM];     // 18.4KB: 4 kernel variants for this o
    __shared__ float att_s[B * KM];
    const size_t ks = (size_t)O * KDIM;
    const float* wp = weights + (size_t)o * KDIM;

    for (int i = threadIdx.x; i < 4 * KDIM; i += 160) {
        int k = i / KDIM, j = i - k * KDIM;
        w4[i] = wp[k * ks + j];
    }
    if (threadIdx.x < B * KM) att_s[threadIdx.x] = g_att[threadIdx.x];
    __syncthreads();

    if (threadIdx.x >= 144) return;
    int t = threadIdx.x / 16;          // tap 0..8
    int g = threadIdx.x % 16;          // channel group (8 channels)
    int c0 = g * 8;

    // per-thread weights: [k][8 channels] for (o, tap t)
    float wr[4][8];
    #pragma unroll
    for (int k = 0; k < 4; k++)
        #pragma unroll
        for (int j = 0; j < 8; j++)
            wr[k][j] = w4[k * KDIM + (c0 + j) * 9 + t];   // inner layout [c][tap]

    __half* dst0 = g_wk + (size_t)o * KDIM + (size_t)t * C + c0;
    #pragma unroll 1
    for (int b = 0; b < B; b++) {
        float a0 = att_s[b * KM + 0], a1 = att_s[b * KM + 1];
        float a2 = att_s[b * KM + 2], a3 = att_s[b * KM + 3];
        __half hb[8];
        #pragma unroll
        for (int j = 0; j < 8; j++) {
            float v = a0 * wr[0][j] + a1 * wr[1][j] + a2 * wr[2][j] + a3 * wr[3][j];
            hb[j] = __float2half_rn(v);
        }
        *(uint4*)(dst0 + (size_t)b * O * KDIM) = *(const uint4*)hb;
    }
}

// ---------------------------------------------------------------------------
// 4) Conv GEMM via mma.sync fp16 (fp32 acc) — best-known config (r9/r13).
//    CTA: M=128 x N=128, 256 threads (8 warps), warp tile 32x64 (4M x 2N).
//    Single-stage buffer, 2 CTAs/SM co-residency does the double buffering.
//    9 stages (one tap each, K=128), cp.async.bulk 256B rows.
// ---------------------------------------------------------------------------
#define RPADB   272
#define A_ROWS  128
#define B_ROWS  128
#define AT_BYTES (A_ROWS * RPADB)         // 34816
#define BT_BYTES (B_ROWS * RPADB)         // 34816
#define OFF_A   0
#define OFF_B   (AT_BYTES)
#define STAGE_BYTES (AT_BYTES + BT_BYTES) // 69632
#define NSTAGE  9
#define STAGE_TX (256u * 256u)            // 65536 bytes per stage
#define CONV_SMEM (1024 + STAGE_BYTES)    // 70656

__global__ void __launch_bounds__(256, 2) conv_kernel(float* __restrict__ out) {
    extern __shared__ char smem[];
    uint32_t sb = smem_to_u32(smem);
    uint32_t mbar = sb;
    uint32_t tiles = sb + 1024;
    int tid = threadIdx.x;
    int lane = tid & 31, wid = tid >> 5;
    int b  = blockIdx.z;
    int m0 = blockIdx.y * 128;
    int n0 = blockIdx.x * 128;
    int wm = (wid & 3) * 32;       // warp M offset (4 M-groups)
    int wn = (wid >> 2) * 64;      // warp N offset (2 N-groups)

    if (tid == 0) MBARRIER_INIT(mbar, 1);
    __syncthreads();

    const __half* wk = g_wk + ((size_t)b * O + m0) * KDIM;
    const __half* xt = g_xt + (size_t)b * HW * C;

    auto load_stage = [&](int s) {
        FENCE_PROXY_ASYNC();
        if (tid == 0) MBARRIER_ARRIVE_EXPECT_TX(mbar, STAGE_TX);
        __syncthreads();
        int tap = s;
        int dy = tap / 3 - 1, dx = tap % 3 - 1;
        if (tid < 128) {
            cp_bulk(tiles + OFF_A + (uint32_t)tid * RPADB,
                    wk + (size_t)tid * KDIM + (size_t)tap * C, 256, mbar);
        } else {
            int row = tid - 128;
            int p = n0 + row;
            int iy = (p >> 6) + dy, ix = (p & 63) + dx;
            bool valid = ((unsigned)iy < 64u) && ((unsigned)ix < 64u);
            const __half* src = valid ? (xt + (size_t)(p + dy * 64 + dx) * C) : g_zero;
            cp_bulk(tiles + OFF_B + (uint32_t)row * RPADB, src, 256, mbar);
        }
    };

    float acc[2][8][4];
    #pragma unroll
    for (int i = 0; i < 2; i++)
        #pragma unroll
        for (int j = 0; j < 8; j++)
            #pragma unroll
            for (int q = 0; q < 4; q++) acc[i][j][q] = 0.f;

    load_stage(0);

    uint32_t a_row = (uint32_t)(wm + (lane & 15));
    uint32_t a_kb  = (uint32_t)((lane >> 4) * 16);
    uint32_t b_row = (uint32_t)(wn + (lane & 7) + ((lane >> 4) & 1) * 8);
    uint32_t b_kb  = (uint32_t)(((lane >> 3) & 1) * 16);

    #pragma unroll 1
    for (int s = 0; s < NSTAGE; s++) {
        MBARRIER_WAIT_PARITY(mbar, s & 1);

        #pragma unroll
        for (int kk = 0; kk < 8; kk++) {
            uint32_t kb = (uint32_t)(kk * 32);      // k16 step = 32B
            uint32_t ah[2][4];
            #pragma unroll
            for (int mt = 0; mt < 2; mt++) {
                uint32_t off = (a_row + mt * 16) * RPADB + kb + a_kb;
                LDSM_X4(ah[mt], tiles + OFF_A + off);
            }
            #pragma unroll
            for (int g = 0; g < 4; g++) {
                uint32_t off = (b_row + g * 16) * RPADB + kb + b_kb;
                uint32_t bh[4];
                LDSM_X4(bh, tiles + OFF_B + off);
                #pragma unroll
                for (int mt = 0; mt < 2; mt++) {
                    #pragma unroll
                    for (int nt = 0; nt < 2; nt++) {
                        mma16816(acc[mt][g * 2 + nt], ah[mt], bh[nt * 2], bh[nt * 2 + 1]);
                    }
                }
            }
        }
        __syncthreads();                 // all reads of the single buffer done
        if (s + 1 < NSTAGE) load_stage(s + 1);
    }

    // epilogue: warp writes 32x64 block
    float* ob = out + ((size_t)b * O + m0) * HW + n0;
    #pragma unroll
    for (int mt = 0; mt < 2; mt++) {
        int r = wm + mt * 16 + (lane >> 2);
        #pragma unroll
        for (int nti = 0; nti < 8; nti++) {
            int cn = wn + nti * 8 + 2 * (lane & 3);
            float2 v0 = make_float2(acc[mt][nti][0], acc[mt][nti][1]);
            float2 v1 = make_float2(acc[mt][nti][2], acc[mt][nti][3]);
            *(float2*)(ob + (size_t)r * HW + cn) = v0;
            *(float2*)(ob + (size_t)(r + 8) * HW + cn) = v1;
        }
    }
    __syncthreads();
    if (tid == 0) MBARRIER_INVAL(mbar);
}

// ---------------------------------------------------------------------------
extern "C" void kernel_launch(void* const* d_in, const int* in_sizes, int n_in,
                              void* d_out, int out_size) {
    const float* x       = (const float*)d_in[0];
    const float* weights = (const float*)d_in[1];
    const float* w1      = (const float*)d_in[2];
    const float* b1      = (const float*)d_in[3];
    const float* w2      = (const float*)d_in[4];
    const float* b2      = (const float*)d_in[5];
    float* out = (float*)d_out;

    zero_kernel<<<1, 128>>>();
    xt_kernel<<<dim3(HW / 64, B), 256>>>(x);
    attn_kernel<<<1, 32>>>(w1, b1, w2, b2);
    wk_kernel<<<O, 160>>>(weights);

    cudaFuncSetAttribute(conv_kernel, cudaFuncAttributeMaxDynamicSharedMemorySize, CONV_SMEM);
    conv_kernel<<<dim3(HW / 128, O / 128, B), 256, CONV_SMEM>>>(out);
}